// round 5
// baseline (speedup 1.0000x reference)
#include <cuda_runtime.h>

typedef unsigned long long ull;

#define BATCH 8
#define CH    64
#define MID   8
#define NPIX  4096
#define TQ    128
#define TJ    64

// Scratch (no allocations allowed -> __device__ globals)
__device__ float g_q[BATCH * NPIX * MID];   // [b][i][m]
__device__ float g_k[BATCH * NPIX * MID];   // [b][j][m]
__device__ float g_v[BATCH * NPIX * CH];    // [b][j][c]

// ---------------------------------------------------------------------------
// Projection kernel: q = Wq x + bq, k = Wk x + bk, v = Wv x + bv  (1x1 convs)
// One thread per pixel. Weights transposed in SMEM for broadcast float4 reads.
// ---------------------------------------------------------------------------
__global__ __launch_bounds__(256) void proj_kernel(
    const float* __restrict__ x,
    const float* __restrict__ wq, const float* __restrict__ bq,
    const float* __restrict__ wk, const float* __restrict__ bk,
    const float* __restrict__ wv, const float* __restrict__ bv)
{
    __shared__ float s_wvT[CH * CH];     // [c][d]
    __shared__ float s_wqT[CH * MID];    // [c][m]
    __shared__ float s_wkT[CH * MID];    // [c][m]
    __shared__ float s_bq[MID], s_bk[MID], s_bv[CH];

    const int tid = threadIdx.x;
    for (int idx = tid; idx < CH * CH; idx += 256) {
        int d = idx >> 6, c = idx & 63;
        s_wvT[c * CH + d] = wv[idx];
    }
    for (int idx = tid; idx < MID * CH; idx += 256) {
        int m = idx >> 6, c = idx & 63;
        s_wqT[c * MID + m] = wq[idx];
        s_wkT[c * MID + m] = wk[idx];
    }
    if (tid < MID) { s_bq[tid] = bq[tid]; s_bk[tid] = bk[tid]; }
    if (tid < CH)  { s_bv[tid] = bv[tid]; }
    __syncthreads();

    const int g = blockIdx.x * 256 + tid;    // global pixel id = b*NPIX + n
    const int b = g >> 12;
    const int n = g & (NPIX - 1);

    float q[MID], k[MID], v[CH];
    #pragma unroll
    for (int m = 0; m < MID; m++) { q[m] = s_bq[m]; k[m] = s_bk[m]; }
    #pragma unroll
    for (int d = 0; d < CH; d++) v[d] = s_bv[d];

    const float* xp = x + (size_t)b * CH * NPIX + n;
    for (int c = 0; c < CH; c++) {
        float xv = xp[(size_t)c * NPIX];
        #pragma unroll
        for (int m = 0; m < MID; m++) {
            q[m] = fmaf(s_wqT[c * MID + m], xv, q[m]);
            k[m] = fmaf(s_wkT[c * MID + m], xv, k[m]);
        }
        #pragma unroll
        for (int d = 0; d < CH; d++)
            v[d] = fmaf(s_wvT[c * CH + d], xv, v[d]);
    }

    float4* qo = (float4*)&g_q[(size_t)g * MID];
    qo[0] = make_float4(q[0], q[1], q[2], q[3]);
    qo[1] = make_float4(q[4], q[5], q[6], q[7]);
    float4* ko = (float4*)&g_k[(size_t)g * MID];
    ko[0] = make_float4(k[0], k[1], k[2], k[3]);
    ko[1] = make_float4(k[4], k[5], k[6], k[7]);
    float4* vo = (float4*)&g_v[(size_t)g * CH];
    #pragma unroll
    for (int r = 0; r < 16; r++)
        vo[r] = make_float4(v[4 * r], v[4 * r + 1], v[4 * r + 2], v[4 * r + 3]);
}

// ---------------------------------------------------------------------------
// Attention kernel. One block = (batch b, 128-query tile).
// Unnormalized softmax (safe for these magnitudes in fp32):
//   num[i][c] = sum_j exp(q_i . k_j) * v[c][j],  Z_i = sum_j exp(q_i . k_j)
//   out = x + gamma * num / Z
// PV accumulation uses packed fma.rn.f32x2 (2x fp32 FMA rate on sm_103a).
// ---------------------------------------------------------------------------
#define FMA_X2(acc, a, bb) \
    asm("fma.rn.f32x2 %0, %1, %2, %0;" : "+l"(acc) : "l"(a), "l"(bb))

// dyn SMEM layout (floats):
//  q_s : [0,      1024)   TQ*8
//  k_s : [1024,   1536)   TJ*8
//  z_s : [1536,   1792)   TQ*2 partial Z
//  e_s : [1792,   9984)   TJ*TQ exp tile  (reused as out staging)
//  v_s : [9984,  18176)   TJ*CH float2 {v,v}
#define SMEM_FLOATS 18176
#define SMEM_BYTES  (SMEM_FLOATS * 4)

__global__ __launch_bounds__(256) void attn_kernel(
    const float* __restrict__ x,
    const float* __restrict__ gamma,
    float* __restrict__ out)
{
    extern __shared__ float smem[];
    float*  q_s = smem;
    float*  k_s = smem + 1024;
    float*  z_s = smem + 1536;
    float*  e_s = smem + 1792;
    float2* v_s = (float2*)(smem + 9984);

    const int tid = threadIdx.x;
    const int b   = blockIdx.y;
    const int i0g = blockIdx.x * TQ;

    // load 128 queries (1024 floats) + zero Z partials
    ((float4*)q_s)[tid] =
        ((const float4*)(g_q + ((size_t)b * NPIX + i0g) * MID))[tid];
    z_s[tid] = 0.0f;
    __syncthreads();

    // E-phase mapping: 1 query per thread, half the j-tile each
    const int il = tid & 127;
    const int jh = tid >> 7;
    const float4 qa = ((const float4*)q_s)[il * 2];
    const float4 qb = ((const float4*)q_s)[il * 2 + 1];

    // GEMM mapping: 8 i-rows (4 pairs) x 4 channels per thread
    const int ti = tid & 15, tc = tid >> 4;
    const int i0 = ti * 8,   c0 = tc * 4;

    ull acc[4][4];
    #pragma unroll
    for (int p = 0; p < 4; p++)
        #pragma unroll
        for (int cc = 0; cc < 4; cc++) acc[p][cc] = 0ull;

    const float* kg_base = g_k + (size_t)b * NPIX * MID;
    const float* vg_base = g_v + (size_t)b * NPIX * CH;

    for (int jt = 0; jt < NPIX / TJ; jt++) {
        const int j0 = jt * TJ;
        __syncthreads();  // previous GEMM done reading e_s/v_s

        if (tid < 128)
            ((float4*)k_s)[tid] = ((const float4*)(kg_base + (size_t)j0 * MID))[tid];
        const float* vg = vg_base + (size_t)j0 * CH;
        #pragma unroll
        for (int r = 0; r < 16; r++) {
            int idx = r * 256 + tid;
            float vv = vg[idx];
            v_s[idx] = make_float2(vv, vv);
        }
        __syncthreads();

        // ---- E phase: e = exp(q.k), accumulate partial Z ----
        float zloc = 0.0f;
        #pragma unroll 4
        for (int jj = 0; jj < 32; jj++) {
            int j = jh * 32 + jj;
            float4 ka = ((const float4*)k_s)[j * 2];
            float4 kb = ((const float4*)k_s)[j * 2 + 1];
            float s = qa.x * ka.x + qa.y * ka.y + qa.z * ka.z + qa.w * ka.w
                    + qb.x * kb.x + qb.y * kb.y + qb.z * kb.z + qb.w * kb.w;
            float e = __expf(s);
            zloc += e;
            e_s[j * 128 + il] = e;
        }
        z_s[il * 2 + jh] += zloc;   // unique owner per (il, jh)
        __syncthreads();

        // ---- GEMM phase: acc += E_pair * {v,v}  (packed f32x2) ----
        #pragma unroll 2
        for (int j = 0; j < TJ; j++) {
            ulonglong2 eA = *(const ulonglong2*)&e_s[j * 128 + i0];
            ulonglong2 eB = *(const ulonglong2*)&e_s[j * 128 + i0 + 4];
            ull vp0 = *(const ull*)&v_s[j * 64 + c0 + 0];
            ull vp1 = *(const ull*)&v_s[j * 64 + c0 + 1];
            ull vp2 = *(const ull*)&v_s[j * 64 + c0 + 2];
            ull vp3 = *(const ull*)&v_s[j * 64 + c0 + 3];
            FMA_X2(acc[0][0], eA.x, vp0); FMA_X2(acc[0][1], eA.x, vp1);
            FMA_X2(acc[0][2], eA.x, vp2); FMA_X2(acc[0][3], eA.x, vp3);
            FMA_X2(acc[1][0], eA.y, vp0); FMA_X2(acc[1][1], eA.y, vp1);
            FMA_X2(acc[1][2], eA.y, vp2); FMA_X2(acc[1][3], eA.y, vp3);
            FMA_X2(acc[2][0], eB.x, vp0); FMA_X2(acc[2][1], eB.x, vp1);
            FMA_X2(acc[2][2], eB.x, vp2); FMA_X2(acc[2][3], eB.x, vp3);
            FMA_X2(acc[3][0], eB.y, vp0); FMA_X2(acc[3][1], eB.y, vp1);
            FMA_X2(acc[3][2], eB.y, vp2); FMA_X2(acc[3][3], eB.y, vp3);
        }
    }
    __syncthreads();   // all GEMM reads of e_s done -> reuse as out staging

    // stage num[i][c] into out_s[c][i] for coalesced writes
    float* out_s = e_s;  // 64*128 floats
    #pragma unroll
    for (int p = 0; p < 4; p++)
        #pragma unroll
        for (int cc = 0; cc < 4; cc++) {
            float2 f = *(float2*)&acc[p][cc];
            *(float2*)&out_s[(c0 + cc) * 128 + i0 + 2 * p] = f;
        }
    // reciprocal Z into (now-dead) q_s
    if (tid < 128) q_s[tid] = 1.0f / (z_s[tid * 2] + z_s[tid * 2 + 1]);
    __syncthreads();

    const float gm = gamma[0];
    #pragma unroll
    for (int r = 0; r < 32; r++) {
        int e  = r * 256 + tid;
        int c  = e >> 7;
        int ii = e & 127;
        size_t gi = ((size_t)(b * CH + c)) * NPIX + i0g + ii;
        out[gi] = x[gi] + gm * out_s[e] * q_s[ii];
    }
}

// ---------------------------------------------------------------------------
extern "C" void kernel_launch(void* const* d_in, const int* in_sizes, int n_in,
                              void* d_out, int out_size)
{
    const float* x     = (const float*)d_in[0];
    const float* wq    = (const float*)d_in[1];
    const float* bq    = (const float*)d_in[2];
    const float* wk    = (const float*)d_in[3];
    const float* bk    = (const float*)d_in[4];
    const float* wv    = (const float*)d_in[5];
    const float* bv    = (const float*)d_in[6];
    const float* gamma = (const float*)d_in[7];
    float* out = (float*)d_out;

    cudaFuncSetAttribute(attn_kernel,
                         cudaFuncAttributeMaxDynamicSharedMemorySize,
                         SMEM_BYTES);

    proj_kernel<<<(BATCH * NPIX) / 256, 256>>>(x, wq, bq, wk, bk, wv, bv);
    attn_kernel<<<dim3(NPIX / TQ, BATCH), 256, SMEM_BYTES>>>(x, gamma, out);
}

// round 6
// speedup vs baseline: 1.0027x; 1.0027x over previous
#include <cuda_runtime.h>

typedef unsigned long long ull;

#define BATCH 8
#define CH    64
#define MID   8
#define NPIX  4096
#define TQ    128
#define TJ    64

// Scratch (no allocations allowed -> __device__ globals)
__device__ float g_q[BATCH * NPIX * MID];   // [b][i][m]
__device__ float g_k[BATCH * NPIX * MID];   // [b][j][m]
__device__ float g_v[BATCH * NPIX * CH];    // [b][j][c]

// ---------------------------------------------------------------------------
// Projection kernel: q = Wq x + bq, k = Wk x + bk, v = Wv x + bv  (1x1 convs)
// One thread per pixel. Weights transposed in SMEM for broadcast float4 reads.
// ---------------------------------------------------------------------------
__global__ __launch_bounds__(256) void proj_kernel(
    const float* __restrict__ x,
    const float* __restrict__ wq, const float* __restrict__ bq,
    const float* __restrict__ wk, const float* __restrict__ bk,
    const float* __restrict__ wv, const float* __restrict__ bv)
{
    __shared__ float s_wvT[CH * CH];     // [c][d]
    __shared__ float s_wqT[CH * MID];    // [c][m]
    __shared__ float s_wkT[CH * MID];    // [c][m]
    __shared__ float s_bq[MID], s_bk[MID], s_bv[CH];

    const int tid = threadIdx.x;
    for (int idx = tid; idx < CH * CH; idx += 256) {
        int d = idx >> 6, c = idx & 63;
        s_wvT[c * CH + d] = wv[idx];
    }
    for (int idx = tid; idx < MID * CH; idx += 256) {
        int m = idx >> 6, c = idx & 63;
        s_wqT[c * MID + m] = wq[idx];
        s_wkT[c * MID + m] = wk[idx];
    }
    if (tid < MID) { s_bq[tid] = bq[tid]; s_bk[tid] = bk[tid]; }
    if (tid < CH)  { s_bv[tid] = bv[tid]; }
    __syncthreads();

    const int g = blockIdx.x * 256 + tid;    // global pixel id = b*NPIX + n
    const int b = g >> 12;
    const int n = g & (NPIX - 1);

    float q[MID], k[MID], v[CH];
    #pragma unroll
    for (int m = 0; m < MID; m++) { q[m] = s_bq[m]; k[m] = s_bk[m]; }
    #pragma unroll
    for (int d = 0; d < CH; d++) v[d] = s_bv[d];

    const float* xp = x + (size_t)b * CH * NPIX + n;
    for (int c = 0; c < CH; c++) {
        float xv = xp[(size_t)c * NPIX];
        #pragma unroll
        for (int m = 0; m < MID; m++) {
            q[m] = fmaf(s_wqT[c * MID + m], xv, q[m]);
            k[m] = fmaf(s_wkT[c * MID + m], xv, k[m]);
        }
        #pragma unroll
        for (int d = 0; d < CH; d++)
            v[d] = fmaf(s_wvT[c * CH + d], xv, v[d]);
    }

    float4* qo = (float4*)&g_q[(size_t)g * MID];
    qo[0] = make_float4(q[0], q[1], q[2], q[3]);
    qo[1] = make_float4(q[4], q[5], q[6], q[7]);
    float4* ko = (float4*)&g_k[(size_t)g * MID];
    ko[0] = make_float4(k[0], k[1], k[2], k[3]);
    ko[1] = make_float4(k[4], k[5], k[6], k[7]);
    float4* vo = (float4*)&g_v[(size_t)g * CH];
    #pragma unroll
    for (int r = 0; r < 16; r++)
        vo[r] = make_float4(v[4 * r], v[4 * r + 1], v[4 * r + 2], v[4 * r + 3]);
}

// ---------------------------------------------------------------------------
// Attention kernel. One block = (batch b, 128-query tile).
// Unnormalized softmax (safe for these magnitudes in fp32):
//   num[i][c] = sum_j exp(q_i . k_j) * v[c][j],  Z_i = sum_j exp(q_i . k_j)
//   out = x + gamma * num / Z
// PV accumulation uses packed fma.rn.f32x2 (2x fp32 FMA rate on sm_103a).
// ---------------------------------------------------------------------------
#define FMA_X2(acc, a, bb) \
    asm("fma.rn.f32x2 %0, %1, %2, %0;" : "+l"(acc) : "l"(a), "l"(bb))

// dyn SMEM layout (floats):
//  q_s : [0,      1024)   TQ*8
//  k_s : [1024,   1536)   TJ*8
//  z_s : [1536,   1792)   TQ*2 partial Z
//  e_s : [1792,   9984)   TJ*TQ exp tile  (reused as out staging)
//  v_s : [9984,  18176)   TJ*CH float2 {v,v}
#define SMEM_FLOATS 18176
#define SMEM_BYTES  (SMEM_FLOATS * 4)

__global__ __launch_bounds__(256) void attn_kernel(
    const float* __restrict__ x,
    const float* __restrict__ gamma,
    float* __restrict__ out)
{
    extern __shared__ float smem[];
    float*  q_s = smem;
    float*  k_s = smem + 1024;
    float*  z_s = smem + 1536;
    float*  e_s = smem + 1792;
    float2* v_s = (float2*)(smem + 9984);

    const int tid = threadIdx.x;
    const int b   = blockIdx.y;
    const int i0g = blockIdx.x * TQ;

    // load 128 queries (1024 floats) + zero Z partials
    ((float4*)q_s)[tid] =
        ((const float4*)(g_q + ((size_t)b * NPIX + i0g) * MID))[tid];
    z_s[tid] = 0.0f;
    __syncthreads();

    // E-phase mapping: 1 query per thread, half the j-tile each
    const int il = tid & 127;
    const int jh = tid >> 7;
    const float4 qa = ((const float4*)q_s)[il * 2];
    const float4 qb = ((const float4*)q_s)[il * 2 + 1];

    // GEMM mapping: 8 i-rows (4 pairs) x 4 channels per thread
    const int ti = tid & 15, tc = tid >> 4;
    const int i0 = ti * 8,   c0 = tc * 4;

    ull acc[4][4];
    #pragma unroll
    for (int p = 0; p < 4; p++)
        #pragma unroll
        for (int cc = 0; cc < 4; cc++) acc[p][cc] = 0ull;

    const float* kg_base = g_k + (size_t)b * NPIX * MID;
    const float* vg_base = g_v + (size_t)b * NPIX * CH;

    for (int jt = 0; jt < NPIX / TJ; jt++) {
        const int j0 = jt * TJ;
        __syncthreads();  // previous GEMM done reading e_s/v_s

        if (tid < 128)
            ((float4*)k_s)[tid] = ((const float4*)(kg_base + (size_t)j0 * MID))[tid];
        const float* vg = vg_base + (size_t)j0 * CH;
        #pragma unroll
        for (int r = 0; r < 16; r++) {
            int idx = r * 256 + tid;
            float vv = vg[idx];
            v_s[idx] = make_float2(vv, vv);
        }
        __syncthreads();

        // ---- E phase: e = exp(q.k), accumulate partial Z ----
        float zloc = 0.0f;
        #pragma unroll 4
        for (int jj = 0; jj < 32; jj++) {
            int j = jh * 32 + jj;
            float4 ka = ((const float4*)k_s)[j * 2];
            float4 kb = ((const float4*)k_s)[j * 2 + 1];
            float s = qa.x * ka.x + qa.y * ka.y + qa.z * ka.z + qa.w * ka.w
                    + qb.x * kb.x + qb.y * kb.y + qb.z * kb.z + qb.w * kb.w;
            float e = __expf(s);
            zloc += e;
            e_s[j * 128 + il] = e;
        }
        z_s[il * 2 + jh] += zloc;   // unique owner per (il, jh)
        __syncthreads();

        // ---- GEMM phase: acc += E_pair * {v,v}  (packed f32x2) ----
        #pragma unroll 2
        for (int j = 0; j < TJ; j++) {
            ulonglong2 eA = *(const ulonglong2*)&e_s[j * 128 + i0];
            ulonglong2 eB = *(const ulonglong2*)&e_s[j * 128 + i0 + 4];
            ull vp0 = *(const ull*)&v_s[j * 64 + c0 + 0];
            ull vp1 = *(const ull*)&v_s[j * 64 + c0 + 1];
            ull vp2 = *(const ull*)&v_s[j * 64 + c0 + 2];
            ull vp3 = *(const ull*)&v_s[j * 64 + c0 + 3];
            FMA_X2(acc[0][0], eA.x, vp0); FMA_X2(acc[0][1], eA.x, vp1);
            FMA_X2(acc[0][2], eA.x, vp2); FMA_X2(acc[0][3], eA.x, vp3);
            FMA_X2(acc[1][0], eA.y, vp0); FMA_X2(acc[1][1], eA.y, vp1);
            FMA_X2(acc[1][2], eA.y, vp2); FMA_X2(acc[1][3], eA.y, vp3);
            FMA_X2(acc[2][0], eB.x, vp0); FMA_X2(acc[2][1], eB.x, vp1);
            FMA_X2(acc[2][2], eB.x, vp2); FMA_X2(acc[2][3], eB.x, vp3);
            FMA_X2(acc[3][0], eB.y, vp0); FMA_X2(acc[3][1], eB.y, vp1);
            FMA_X2(acc[3][2], eB.y, vp2); FMA_X2(acc[3][3], eB.y, vp3);
        }
    }
    __syncthreads();   // all GEMM reads of e_s done -> reuse as out staging

    // stage num[i][c] into out_s[c][i] for coalesced writes
    float* out_s = e_s;  // 64*128 floats
    #pragma unroll
    for (int p = 0; p < 4; p++)
        #pragma unroll
        for (int cc = 0; cc < 4; cc++) {
            float2 f = *(float2*)&acc[p][cc];
            *(float2*)&out_s[(c0 + cc) * 128 + i0 + 2 * p] = f;
        }
    // reciprocal Z into (now-dead) q_s
    if (tid < 128) q_s[tid] = 1.0f / (z_s[tid * 2] + z_s[tid * 2 + 1]);
    __syncthreads();

    const float gm = gamma[0];
    #pragma unroll
    for (int r = 0; r < 32; r++) {
        int e  = r * 256 + tid;
        int c  = e >> 7;
        int ii = e & 127;
        size_t gi = ((size_t)(b * CH + c)) * NPIX + i0g + ii;
        out[gi] = x[gi] + gm * out_s[e] * q_s[ii];
    }
}

// ---------------------------------------------------------------------------
extern "C" void kernel_launch(void* const* d_in, const int* in_sizes, int n_in,
                              void* d_out, int out_size)
{
    const float* x     = (const float*)d_in[0];
    const float* wq    = (const float*)d_in[1];
    const float* bq    = (const float*)d_in[2];
    const float* wk    = (const float*)d_in[3];
    const float* bk    = (const float*)d_in[4];
    const float* wv    = (const float*)d_in[5];
    const float* bv    = (const float*)d_in[6];
    const float* gamma = (const float*)d_in[7];
    float* out = (float*)d_out;

    cudaFuncSetAttribute(attn_kernel,
                         cudaFuncAttributeMaxDynamicSharedMemorySize,
                         SMEM_BYTES);

    proj_kernel<<<(BATCH * NPIX) / 256, 256>>>(x, wq, bq, wk, bk, wv, bv);
    attn_kernel<<<dim3(NPIX / TQ, BATCH), 256, SMEM_BYTES>>>(x, gamma, out);
}